// round 15
// baseline (speedup 1.0000x reference)
#include <cuda_runtime.h>
#include <cuda_bf16.h>
#include <math.h>
#include <stdint.h>

// ---------------- problem constants ----------------
#define Bc   2
#define Tc   1024
#define Vc   32000
#define Dc   1024
#define Hc   16
#define Lc   4
#define DHc  64
#define DFFc 2730
#define NTc  (Bc*Tc)
#define EPSf 1e-6f

#define KP_D   3072      // 3*1024
#define KP_FF  8192      // pad(3*2730=8190 -> 8192)
#define KP_ATT 192       // 3*64

// ---------------- scratch (static device globals; no allocs) ----------------
__device__ float g_x  [NTc*Dc];
__device__ float g_qkv[NTc*3*Dc];
__device__ float g_tmp[(size_t)NTc*2*DFFc];
__device__ float g_rs [Bc*Hc*Tc];
__device__ __nv_bfloat16 g_a3[(size_t)NTc*KP_FF];          // activation split (A form: hi|lo|hi)
__device__ __nv_bfloat16 g_wb[(size_t)Vc*KP_D];            // weight split (B form: hi|hi|lo)
__device__ __nv_bfloat16 g_q3[(size_t)Bc*Hc*Tc*KP_ATT];    // A form
__device__ __nv_bfloat16 g_k3[(size_t)Bc*Hc*Tc*KP_ATT];    // B form
__device__ __nv_bfloat16 g_v3[(size_t)Bc*Hc*DHc*KP_D];     // B form, V^T [bz][d][3072]
__device__ __nv_bfloat16 g_s3[(size_t)Bc*Hc*Tc*KP_D];      // A form, s4 [bz][t][3072]

__device__ __forceinline__ float rsig(float x) {
    return 0.5f * (x / (fabsf(x) + 1.0f) + 1.0f);
}
__device__ __forceinline__ void split2(float v, __nv_bfloat16& hi, __nv_bfloat16& lo) {
    hi = __float2bfloat16(v);
    lo = __float2bfloat16(v - __bfloat162float(hi));
}
__device__ __forceinline__ uint32_t pack_bf2(float a, float b) {
    __nv_bfloat162 t = __floats2bfloat162_rn(a, b);
    return *reinterpret_cast<uint32_t*>(&t);
}

// ---------------- PTX helpers (sm_80+ baseline) ----------------
__device__ __forceinline__ uint32_t s2u(const void* p) {
    uint32_t a;
    asm("{ .reg .u64 t; cvta.to.shared.u64 t, %1; cvt.u32.u64 %0, t; }" : "=r"(a) : "l"(p));
    return a;
}
__device__ __forceinline__ void cp16(uint32_t dst, const void* src, bool pred) {
    int sz = pred ? 16 : 0;
    asm volatile("cp.async.cg.shared.global [%0], [%1], 16, %2;"
                 :: "r"(dst), "l"(src), "r"(sz) : "memory");
}
__device__ __forceinline__ void cp_commit() {
    asm volatile("cp.async.commit_group;" ::: "memory");
}
__device__ __forceinline__ void cp_wait0() {
    asm volatile("cp.async.wait_group 0;" ::: "memory");
}
__device__ __forceinline__ void mma16816(float* c, const uint32_t* a, uint32_t b0, uint32_t b1) {
    asm volatile("mma.sync.aligned.m16n8k16.row.col.f32.bf16.bf16.f32 "
                 "{%0,%1,%2,%3}, {%4,%5,%6,%7}, {%8,%9}, {%0,%1,%2,%3};"
                 : "+f"(c[0]), "+f"(c[1]), "+f"(c[2]), "+f"(c[3])
                 : "r"(a[0]), "r"(a[1]), "r"(a[2]), "r"(a[3]), "r"(b0), "r"(b1));
}

// ---------------- HMMA GEMM: C[M,N] = A'[M,Kp] @ B'[N,Kp]^T ----------------
// BM=128 BN=128 BK=64. 2-stage double buffer (NSTG=2 so TWO CTAs fit per SM:
// 2 x 72KB smem = 144KB << 228KB; R14 showed NSTG=3's 108KB blocked the 2nd
// CTA). Cross-CTA overlap replaces the 3rd stage for latency hiding.
// One __syncthreads per k-iter; wait_group 0 at loop top (with one prologue
// group, the stage about to be read must be fully landed).
// 8 warps (2m x 4n), warp tile 64x32. Padded smem rows (144B), direct u32
// fragment loads. EP_SCORES: fully-masked causal tiles skipped.
// EP_PV: k-range truncated per block to keys <= m0+127 within each segment.
enum { EP_NONE = 0, EP_ADD = 1, EP_SCORES = 2, EP_PV = 3 };

#define BKc       64
#define SROW      144                 // 128B data + 16B pad
#define TILE_BYT  (128 * SROW)        // 18432 per operand tile
#define STAGE_BYT (2 * TILE_BYT)      // A + B per stage
#define NSTG      2
#define SMEM_TOT  (NSTG * STAGE_BYT)  // 73728

template<int EPI>
__global__ void __launch_bounds__(256, 2)
gemm_mma(const __nv_bfloat16* __restrict__ A, const __nv_bfloat16* __restrict__ B,
         float* __restrict__ C, int M, int N, int Kp,
         long long sA, long long sB, const float* __restrict__ rdiv)
{
    extern __shared__ __align__(16) char smem[];

    const int tid  = threadIdx.x;
    const int lane = tid & 31, wid = tid >> 5;
    const int wm   = wid >> 2, wn = wid & 3;
    const int bz   = blockIdx.z;
    const int m0   = blockIdx.x * 128;
    const int n0   = blockIdx.y * 128;

    // ---- fully-masked causal tile: write zero splits, done ----
    if (EPI == EP_SCORES && m0 + 127 < n0) {
        #pragma unroll
        for (int fm = 0; fm < 4; fm++) {
            const int gmr = m0 + wm * 64 + fm * 16 + (lane >> 2);
            #pragma unroll
            for (int ng = 0; ng < 4; ng++) {
                const int gn = n0 + wn * 32 + ng * 8 + (lane & 3) * 2;
                #pragma unroll
                for (int hh = 0; hh < 2; hh++) {
                    const int gm = gmr + hh * 8;
                    __nv_bfloat16* rowp = g_s3 + ((size_t)bz * Tc + gm) * KP_D;
                    *(uint32_t*)(rowp + gn)        = 0u;
                    *(uint32_t*)(rowp + 1024 + gn) = 0u;
                    *(uint32_t*)(rowp + 2048 + gn) = 0u;
                }
            }
        }
        return;
    }

    const __nv_bfloat16* Ab = A + (long long)bz * sA + (long long)m0 * Kp;
    const __nv_bfloat16* Bb = B + (long long)bz * sB;

    const uint32_t sbase = s2u(smem);
    const int nk = Kp >> 6;

    // PV: iterate 3 segments x lim tiles; others: nk linear tiles
    int lim, niter;
    if (EPI == EP_PV) {
        lim = m0 / 64 + 2; if (lim > 16) lim = 16;
        niter = 3 * lim;
    } else {
        lim = nk; niter = nk;
    }
    // k-tile index for logical iter j
    #define KOFF(j) ((EPI == EP_PV) ? (((j) / lim) * 16 + ((j) % lim)) : (j))

    // copy coords: 1024 16B-chunks per tile (128 rows x 8 chunks), 4 per thread
    int cr[4], cc[4];
    #pragma unroll
    for (int i = 0; i < 4; i++) { int e = tid + i * 256; cr[i] = e >> 3; cc[i] = e & 7; }

    // ---- prologue: stage 0 ----
    {
        const int kk = KOFF(0);
        uint32_t da = sbase;
        uint32_t db = da + TILE_BYT;
        #pragma unroll
        for (int i = 0; i < 4; i++) {
            const char* srcA = (const char*)(Ab + (long long)cr[i] * Kp + kk * BKc) + cc[i] * 16;
            cp16(da + cr[i] * SROW + cc[i] * 16, srcA, true);
            bool v = (n0 + cr[i]) < N;
            int rB = v ? (n0 + cr[i]) : 0;
            const char* srcB = (const char*)(Bb + (long long)rB * Kp + kk * BKc) + cc[i] * 16;
            cp16(db + cr[i] * SROW + cc[i] * 16, srcB, v);
        }
        cp_commit();
    }

    float acc[4][4][4] = {};

    for (int j = 0; j < niter; j++) {
        cp_wait0();        // stage j fully landed
        __syncthreads();   // all warps done reading buf[(j-1)&1] (overwritten next)

        // prefetch stage j+1 into the buffer last read at iter j-1;
        // it loads while compute of stage j runs below.
        const int nxt = j + 1;
        if (nxt < niter) {
            const int kk = KOFF(nxt);
            uint32_t da = sbase + (nxt & 1) * STAGE_BYT;
            uint32_t db = da + TILE_BYT;
            #pragma unroll
            for (int i = 0; i < 4; i++) {
                const char* srcA = (const char*)(Ab + (long long)cr[i] * Kp + kk * BKc) + cc[i] * 16;
                cp16(da + cr[i] * SROW + cc[i] * 16, srcA, true);
                bool v = (n0 + cr[i]) < N;
                int rB = v ? (n0 + cr[i]) : 0;
                const char* srcB = (const char*)(Bb + (long long)rB * Kp + kk * BKc) + cc[i] * 16;
                cp16(db + cr[i] * SROW + cc[i] * 16, srcB, v);
            }
        }
        cp_commit();       // empty-group commits keep wait_group accounting uniform

        const char* sa = smem + (j & 1) * STAGE_BYT;
        const char* sb = sa + TILE_BYT;

        #pragma unroll
        for (int ks = 0; ks < 4; ks++) {
            // A fragments per PTX m16n8k16 A table:
            // reg r: row = base + lane/4 + (r&1)*8 ; k = ks*16 + 2*(lane&3) + (r>>1)*8
            uint32_t af[4][4];
            #pragma unroll
            for (int fm = 0; fm < 4; fm++) {
                const int rbase = wm * 64 + fm * 16 + (lane >> 2);
                const int kb    = ks * 16 + 2 * (lane & 3);
                #pragma unroll
                for (int r = 0; r < 4; r++) {
                    int row = rbase + (r & 1) * 8;
                    int kk  = kb + (r >> 1) * 8;
                    af[fm][r] = *(const uint32_t*)(sa + row * SROW + kk * 2);
                }
            }
            // B fragments: reg r: n = base + lane/4 ; k = ks*16 + 2*(lane&3) + r*8
            uint32_t bf[2][2][2];
            #pragma unroll
            for (int fn = 0; fn < 2; fn++)
                #pragma unroll
                for (int sub = 0; sub < 2; sub++) {
                    const int n = wn * 32 + fn * 16 + sub * 8 + (lane >> 2);
                    const int kb = ks * 16 + 2 * (lane & 3);
                    #pragma unroll
                    for (int r = 0; r < 2; r++)
                        bf[fn][sub][r] = *(const uint32_t*)(sb + n * SROW + (kb + r * 8) * 2);
                }
            #pragma unroll
            for (int fm = 0; fm < 4; fm++)
                #pragma unroll
                for (int fn = 0; fn < 2; fn++)
                    #pragma unroll
                    for (int sub = 0; sub < 2; sub++)
                        mma16816(acc[fm][fn * 2 + sub], af[fm],
                                 bf[fn][sub][0], bf[fn][sub][1]);
        }
    }
    #undef KOFF

    // ---------------- epilogue ----------------
    #pragma unroll
    for (int fm = 0; fm < 4; fm++) {
        const int gmr = m0 + wm * 64 + fm * 16 + (lane >> 2);
        #pragma unroll
        for (int ng = 0; ng < 4; ng++) {
            const int gn = n0 + wn * 32 + ng * 8 + (lane & 3) * 2;
            #pragma unroll
            for (int hh = 0; hh < 2; hh++) {
                const int gm = gmr + hh * 8;
                float v0 = acc[fm][ng][2 * hh];
                float v1 = acc[fm][ng][2 * hh + 1];

                if (EPI == EP_SCORES) {
                    const int   hd    = bz & (Hc - 1);
                    const float slope = exp2f(-0.5f * (float)(hd + 1));
                    float s0 = v0 * 0.125f - slope * fabsf((float)(gm - gn));
                    float s1 = v1 * 0.125f - slope * fabsf((float)(gm - gn - 1));
                    if (gm < gn)     s0 = -10000.0f;
                    if (gm < gn + 1) s1 = -10000.0f;
                    float q0 = rsig(s0); q0 *= q0; s0 = q0 * q0;
                    float q1 = rsig(s1); q1 *= q1; s1 = q1 * q1;
                    __nv_bfloat16 h0, l0, h1, l1;
                    split2(s0, h0, l0); split2(s1, h1, l1);
                    // s3 is an A operand: [hi | lo | hi]
                    __nv_bfloat16* rowp = g_s3 + ((size_t)bz * Tc + gm) * KP_D;
                    uint32_t hp = pack_bf2(__bfloat162float(h0), __bfloat162float(h1));
                    uint32_t lp = pack_bf2(__bfloat162float(l0), __bfloat162float(l1));
                    *(uint32_t*)(rowp + gn)        = hp;
                    *(uint32_t*)(rowp + 1024 + gn) = lp;
                    *(uint32_t*)(rowp + 2048 + gn) = hp;
                } else if (EPI == EP_PV) {
                    if (gn >= N) continue;
                    const float inv = 1.0f / (rdiv[(size_t)bz * Tc + gm] + EPSf);
                    const int b = bz >> 4, hd = bz & 15;
                    float o0 = v0 * inv, o1 = v1 * inv;
                    __nv_bfloat16 h0, l0, h1, l1;
                    split2(o0, h0, l0); split2(o1, h1, l1);
                    // a3 is an A operand: [hi | lo | hi]
                    __nv_bfloat16* rowp = g_a3 + ((size_t)(b * Tc + gm)) * KP_D;
                    const int col = hd * DHc + gn;
                    uint32_t hp = pack_bf2(__bfloat162float(h0), __bfloat162float(h1));
                    uint32_t lp = pack_bf2(__bfloat162float(l0), __bfloat162float(l1));
                    *(uint32_t*)(rowp + col)        = hp;
                    *(uint32_t*)(rowp + 1024 + col) = lp;
                    *(uint32_t*)(rowp + 2048 + col) = hp;
                } else {
                    if (gn >= N) continue;
                    float* cp = C + (size_t)gm * N + gn;
                    if (EPI == EP_ADD) { cp[0] += v0; cp[1] += v1; }
                    else {
                        float2 t; t.x = v0; t.y = v1;
                        *(float2*)cp = t;
                    }
                }
            }
        }
    }
}

// ---------------- elementwise / reduction kernels ----------------

__global__ void embed_kernel(const int* __restrict__ ids, const float* __restrict__ emb)
{
    long long idx = (long long)blockIdx.x * blockDim.x + threadIdx.x;
    if (idx >= (long long)NTc * Dc) return;
    int tok = (int)(idx / Dc);
    int d   = (int)(idx % Dc);
    g_x[idx] = emb[(long long)ids[tok] * Dc + d];
}

// mean-error norm -> A-form split row [hi | lo | hi] at given stride
__global__ void __launch_bounds__(256)
norm_split_kernel(const float* __restrict__ x, const float* __restrict__ w, int stride)
{
    int row = blockIdx.x;
    const float* xr = x + (long long)row * Dc;
    float s = 0.0f;
    for (int d = threadIdx.x; d < Dc; d += 256) s += fabsf(xr[d]);
    #pragma unroll
    for (int off = 16; off > 0; off >>= 1) s += __shfl_xor_sync(0xffffffffu, s, off);
    __shared__ float red[8];
    int wid = threadIdx.x >> 5, lid = threadIdx.x & 31;
    if (lid == 0) red[wid] = s;
    __syncthreads();
    __shared__ float s_inv;
    if (threadIdx.x == 0) {
        float t = 0.0f;
        #pragma unroll
        for (int i = 0; i < 8; i++) t += red[i];
        s_inv = 1.0f / (t * (1.0f / Dc) + EPSf);
    }
    __syncthreads();
    float inv = s_inv;
    __nv_bfloat16* orow = g_a3 + (size_t)row * stride;
    for (int d = threadIdx.x; d < Dc; d += 256) {
        float v = xr[d] * inv * w[d];
        __nv_bfloat16 hi, lo; split2(v, hi, lo);
        orow[d] = hi; orow[1024 + d] = lo; orow[2048 + d] = hi;
    }
}

// weight fp32 [N,K] -> B-form bf16 split [N,Kp]: [hi K | hi K | lo K | zeros]
__global__ void wcvt_kernel(const float* __restrict__ src, __nv_bfloat16* __restrict__ dst,
                            int N, int K, int Kp)
{
    long long idx = (long long)blockIdx.x * blockDim.x + threadIdx.x;
    if (idx >= (long long)N * Kp) return;
    int n = (int)(idx / Kp);
    int c = (int)(idx % Kp);
    __nv_bfloat16 o;
    if (c < 3 * K) {
        int cc = (c < K) ? c : ((c < 2 * K) ? c - K : c - 2 * K);
        float v = src[(long long)n * K + cc];
        __nv_bfloat16 hi, lo; split2(v, hi, lo);
        o = (c >= 2 * K) ? lo : hi;      // B form: segments [hi | hi | lo]
    } else {
        o = __float2bfloat16(0.0f);
    }
    dst[idx] = o;
}

// split qkv fp32 [tok][3072]:
//   q3 (A operand) -> [hi | lo | hi]
//   k3 (B operand) -> [hi | hi | lo]
//   v3 (B operand, transposed) -> [hi | hi | lo]
__global__ void split_qkv_kernel()
{
    long long idx = (long long)blockIdx.x * blockDim.x + threadIdx.x;
    if (idx >= (long long)NTc * 3 * Dc) return;
    int tok = (int)(idx / (3 * Dc));
    int r   = (int)(idx % (3 * Dc));
    int c   = r / Dc;
    int hd  = r % Dc;
    int h   = hd / DHc;
    int d   = hd % DHc;
    int b   = tok / Tc;
    int t   = tok % Tc;
    float v = g_qkv[idx];
    __nv_bfloat16 hi, lo; split2(v, hi, lo);
    size_t bz = (size_t)(b * Hc + h);
    if (c == 0) {
        __nv_bfloat16* rp = g_q3 + (bz * Tc + t) * KP_ATT;
        rp[d] = hi; rp[64 + d] = lo; rp[128 + d] = hi;       // A form
    } else if (c == 1) {
        __nv_bfloat16* rp = g_k3 + (bz * Tc + t) * KP_ATT;
        rp[d] = hi; rp[64 + d] = hi; rp[128 + d] = lo;       // B form
    } else {
        __nv_bfloat16* rp = g_v3 + (bz * DHc + d) * KP_D;
        rp[t] = hi; rp[1024 + t] = hi; rp[2048 + t] = lo;    // B form
    }
}

// rowsum of s4 from A-form split (hi at +0, lo at +1024)
__global__ void __launch_bounds__(256)
rowsum_kernel()
{
    int row = blockIdx.x;                   // 0 .. B*H*T-1
    const __nv_bfloat16* sr = g_s3 + (size_t)row * KP_D;
    float s = 0.0f;
    for (int j = threadIdx.x; j < Tc; j += 256)
        s += __bfloat162float(sr[j]) + __bfloat162float(sr[1024 + j]);
    #pragma unroll
    for (int off = 16; off > 0; off >>= 1) s += __shfl_xor_sync(0xffffffffu, s, off);
    __shared__ float red[8];
    int wid = threadIdx.x >> 5, lid = threadIdx.x & 31;
    if (lid == 0) red[wid] = s;
    __syncthreads();
    if (threadIdx.x == 0) {
        float t = 0.0f;
        #pragma unroll
        for (int i = 0; i < 8; i++) t += red[i];
        g_rs[row] = t;
    }
}

// swiglu: reads g_tmp [tok][5460], writes A-form split rows into g_a3 at stride 8192
__global__ void swiglu_kernel()
{
    long long idx = (long long)blockIdx.x * blockDim.x + threadIdx.x;
    if (idx >= (long long)NTc * DFFc) return;
    int tok = (int)(idx / DFFc);
    int j   = (int)(idx % DFFc);
    float g = g_tmp[(long long)tok * (2 * DFFc) + j];
    float v = g_tmp[(long long)tok * (2 * DFFc) + DFFc + j];
    float o = g * rsig(g) * v;
    __nv_bfloat16 hi, lo; split2(o, hi, lo);
    __nv_bfloat16* rp = g_a3 + (size_t)tok * KP_FF;
    rp[j] = hi; rp[DFFc + j] = lo; rp[2 * DFFc + j] = hi;
    if (j < 2) rp[3 * DFFc + j] = __float2bfloat16(0.0f);   // pad cols 8190/8191
}

// ---------------- host ----------------

template<int EPI>
static void launch_gemm(const __nv_bfloat16* A, const __nv_bfloat16* B, float* C,
                        int M, int N, int Kp, long long sA, long long sB,
                        int batch, const float* rdiv)
{
    cudaFuncSetAttribute(gemm_mma<EPI>, cudaFuncAttributeMaxDynamicSharedMemorySize, SMEM_TOT);
    dim3 grid(M / 128, (N + 127) / 128, batch);
    gemm_mma<EPI><<<grid, 256, SMEM_TOT>>>(A, B, C, M, N, Kp, sA, sB, rdiv);
}

extern "C" void kernel_launch(void* const* d_in, const int* in_sizes, int n_in,
                              void* d_out, int out_size)
{
    const int*   ids   = (const int*)  d_in[0];
    const float* emb   = (const float*)d_in[1];
    const float* qkv_w = (const float*)d_in[2];
    const float* out_w = (const float*)d_in[3];
    const float* n1_w  = (const float*)d_in[4];
    const float* n2_w  = (const float*)d_in[5];
    const float* wm_w  = (const float*)d_in[6];
    const float* w3_w  = (const float*)d_in[7];
    const float* fn_w  = (const float*)d_in[8];
    float* logits = (float*)d_out;

    float *px, *pqkv, *ptmp, *prs;
    __nv_bfloat16 *pa3, *pwb, *pq3, *pk3, *pv3, *ps3;
    cudaGetSymbolAddress((void**)&px,   g_x);
    cudaGetSymbolAddress((void**)&pqkv, g_qkv);
    cudaGetSymbolAddress((void**)&ptmp, g_tmp);
    cudaGetSymbolAddress((void**)&prs,  g_rs);
    cudaGetSymbolAddress((void**)&pa3,  g_a3);
    cudaGetSymbolAddress((void**)&pwb,  g_wb);
    cudaGetSymbolAddress((void**)&pq3,  g_q3);
    cudaGetSymbolAddress((void**)&pk3,  g_k3);
    cudaGetSymbolAddress((void**)&pv3,  g_v3);
    cudaGetSymbolAddress((void**)&ps3,  g_s3);

    const long long nXD = (long long)NTc * Dc;

    embed_kernel<<<(unsigned)((nXD + 255) / 256), 256>>>(ids, emb);

    for (int l = 0; l < Lc; l++) {
        // ---- attention ----
        norm_split_kernel<<<NTc, 256>>>(px, n1_w + (long long)l * Dc, KP_D);

        wcvt_kernel<<<(unsigned)(((long long)3 * Dc * KP_D + 255) / 256), 256>>>(
            qkv_w + (long long)l * 3 * Dc * Dc, pwb, 3 * Dc, Dc, KP_D);
        launch_gemm<EP_NONE>(pa3, pwb, pqkv, NTc, 3 * Dc, KP_D, 0, 0, 1, nullptr);

        split_qkv_kernel<<<(unsigned)(((long long)NTc * 3 * Dc + 255) / 256), 256>>>();

        // scores + alibi + causal + sigmoid^4 -> split bf16
        launch_gemm<EP_SCORES>(pq3, pk3, nullptr, Tc, Tc, KP_ATT,
                               (long long)Tc * KP_ATT, (long long)Tc * KP_ATT,
                               Bc * Hc, nullptr);

        rowsum_kernel<<<Bc * Hc * Tc, 256>>>();

        // (s4 @ V) / rowsum -> merged-head split directly into a3
        launch_gemm<EP_PV>(ps3, pv3, nullptr, Tc, DHc, KP_D,
                           (long long)Tc * KP_D, (long long)DHc * KP_D,
                           Bc * Hc, prs);

        wcvt_kernel<<<(unsigned)(((long long)Dc * KP_D + 255) / 256), 256>>>(
            out_w + (long long)l * Dc * Dc, pwb, Dc, Dc, KP_D);
        launch_gemm<EP_ADD>(pa3, pwb, px, NTc, Dc, KP_D, 0, 0, 1, nullptr);

        // ---- swiglu ffn ----
        norm_split_kernel<<<NTc, 256>>>(px, n2_w + (long long)l * Dc, KP_D);

        wcvt_kernel<<<(unsigned)(((long long)2 * DFFc * KP_D + 255) / 256), 256>>>(
            wm_w + (long long)l * 2 * DFFc * Dc, pwb, 2 * DFFc, Dc, KP_D);
        launch_gemm<EP_NONE>(pa3, pwb, ptmp, NTc, 2 * DFFc, KP_D, 0, 0, 1, nullptr);

        swiglu_kernel<<<(unsigned)(((long long)NTc * DFFc + 255) / 256), 256>>>();

        wcvt_kernel<<<(unsigned)(((long long)Dc * KP_FF + 255) / 256), 256>>>(
            w3_w + (long long)l * Dc * DFFc, pwb, Dc, DFFc, KP_FF);
        launch_gemm<EP_ADD>(pa3, pwb, px, NTc, Dc, KP_FF, 0, 0, 1, nullptr);
    }

    // ---- final norm + logits ----
    norm_split_kernel<<<NTc, 256>>>(px, fn_w, KP_D);

    wcvt_kernel<<<(unsigned)(((long long)Vc * KP_D + 255) / 256), 256>>>(
        emb, pwb, Vc, Dc, KP_D);
    launch_gemm<EP_NONE>(pa3, pwb, logits, NTc, Vc, KP_D, 0, 0, 1, nullptr);
}

// round 16
// speedup vs baseline: 1.4763x; 1.4763x over previous
#include <cuda_runtime.h>
#include <cuda_bf16.h>
#include <math.h>
#include <stdint.h>

// ---------------- problem constants ----------------
#define Bc   2
#define Tc   1024
#define Vc   32000
#define Dc   1024
#define Hc   16
#define Lc   4
#define DHc  64
#define DFFc 2730
#define NTc  (Bc*Tc)
#define EPSf 1e-6f

#define KP_D   3072      // 3*1024
#define KP_FF  8192      // pad(3*2730=8190 -> 8192)
#define KP_ATT 192       // 3*64

// ---------------- scratch (static device globals; no allocs) ----------------
__device__ float g_x  [NTc*Dc];
__device__ float g_qkv[NTc*3*Dc];
__device__ float g_tmp[(size_t)NTc*2*DFFc];
__device__ float g_rs [Bc*Hc*Tc];
__device__ __nv_bfloat16 g_a3[(size_t)NTc*KP_FF];          // activation split (A form: hi|lo|hi)
__device__ __nv_bfloat16 g_wb[(size_t)Vc*KP_D];            // weight split (B form: hi|hi|lo)
__device__ __nv_bfloat16 g_q3[(size_t)Bc*Hc*Tc*KP_ATT];    // A form
__device__ __nv_bfloat16 g_k3[(size_t)Bc*Hc*Tc*KP_ATT];    // B form
__device__ __nv_bfloat16 g_v3[(size_t)Bc*Hc*DHc*KP_D];     // B form, V^T [bz][d][3072]
__device__ __nv_bfloat16 g_s3[(size_t)Bc*Hc*Tc*KP_D];      // A form, s4 [bz][t][3072]

__device__ __forceinline__ float rsig(float x) {
    return 0.5f * (x / (fabsf(x) + 1.0f) + 1.0f);
}
__device__ __forceinline__ void split2(float v, __nv_bfloat16& hi, __nv_bfloat16& lo) {
    hi = __float2bfloat16(v);
    lo = __float2bfloat16(v - __bfloat162float(hi));
}
__device__ __forceinline__ uint32_t pack_bf2(float a, float b) {
    __nv_bfloat162 t = __floats2bfloat162_rn(a, b);
    return *reinterpret_cast<uint32_t*>(&t);
}

// ---------------- PTX helpers (sm_80+ baseline) ----------------
__device__ __forceinline__ uint32_t s2u(const void* p) {
    uint32_t a;
    asm("{ .reg .u64 t; cvta.to.shared.u64 t, %1; cvt.u32.u64 %0, t; }" : "=r"(a) : "l"(p));
    return a;
}
__device__ __forceinline__ void cp16(uint32_t dst, const void* src, bool pred) {
    int sz = pred ? 16 : 0;
    asm volatile("cp.async.cg.shared.global [%0], [%1], 16, %2;"
                 :: "r"(dst), "l"(src), "r"(sz) : "memory");
}
__device__ __forceinline__ void cp_commit() {
    asm volatile("cp.async.commit_group;" ::: "memory");
}
__device__ __forceinline__ void cp_wait1() {
    asm volatile("cp.async.wait_group 1;" ::: "memory");
}
__device__ __forceinline__ void ldsm4(uint32_t* r, uint32_t addr) {
    asm volatile("ldmatrix.sync.aligned.m8n8.x4.shared.b16 {%0,%1,%2,%3}, [%4];"
                 : "=r"(r[0]), "=r"(r[1]), "=r"(r[2]), "=r"(r[3]) : "r"(addr));
}
__device__ __forceinline__ void mma16816(float* c, const uint32_t* a, uint32_t b0, uint32_t b1) {
    asm volatile("mma.sync.aligned.m16n8k16.row.col.f32.bf16.bf16.f32 "
                 "{%0,%1,%2,%3}, {%4,%5,%6,%7}, {%8,%9}, {%0,%1,%2,%3};"
                 : "+f"(c[0]), "+f"(c[1]), "+f"(c[2]), "+f"(c[3])
                 : "r"(a[0]), "r"(a[1]), "r"(a[2]), "r"(a[3]), "r"(b0), "r"(b1));
}

// ---------------- HMMA GEMM: C[M,N] = A'[M,Kp] @ B'[N,Kp]^T ----------------
// BM=128 BN=128 BK=64. 3-stage cp.async pipeline (R14 config: 108KB smem,
// 2 CTAs/SM resident), one __syncthreads per k-iter. 8 warps (2m x 4n),
// warp tile 64x32. Padded smem rows (144B). Fragment loads via ldmatrix.x4
// with lane-swizzled base offsets HOISTED out of the mainloop (R12's failure
// was per-call address recompute; here the inner loop is bufbase + immediate).
// EP_SCORES: fully-masked causal tiles skipped (write zeros).
// EP_PV: k-range truncated per block to keys <= m0+127 within each segment.
enum { EP_NONE = 0, EP_ADD = 1, EP_SCORES = 2, EP_PV = 3 };

#define BKc       64
#define SROW      144                 // 128B data + 16B pad
#define TILE_BYT  (128 * SROW)        // 18432 per operand tile
#define STAGE_BYT (2 * TILE_BYT)      // A + B per stage
#define NSTG      3
#define SMEM_TOT  (NSTG * STAGE_BYT)  // 110592

template<int EPI>
__global__ void __launch_bounds__(256, 2)
gemm_mma(const __nv_bfloat16* __restrict__ A, const __nv_bfloat16* __restrict__ B,
         float* __restrict__ C, int M, int N, int Kp,
         long long sA, long long sB, const float* __restrict__ rdiv)
{
    extern __shared__ __align__(16) char smem[];

    const int tid  = threadIdx.x;
    const int lane = tid & 31, wid = tid >> 5;
    const int wm   = wid >> 2, wn = wid & 3;
    const int bz   = blockIdx.z;
    const int m0   = blockIdx.x * 128;
    const int n0   = blockIdx.y * 128;

    // ---- fully-masked causal tile: write zero splits, done ----
    if (EPI == EP_SCORES && m0 + 127 < n0) {
        #pragma unroll
        for (int fm = 0; fm < 4; fm++) {
            const int gmr = m0 + wm * 64 + fm * 16 + (lane >> 2);
            #pragma unroll
            for (int ng = 0; ng < 4; ng++) {
                const int gn = n0 + wn * 32 + ng * 8 + (lane & 3) * 2;
                #pragma unroll
                for (int hh = 0; hh < 2; hh++) {
                    const int gm = gmr + hh * 8;
                    __nv_bfloat16* rowp = g_s3 + ((size_t)bz * Tc + gm) * KP_D;
                    *(uint32_t*)(rowp + gn)        = 0u;
                    *(uint32_t*)(rowp + 1024 + gn) = 0u;
                    *(uint32_t*)(rowp + 2048 + gn) = 0u;
                }
            }
        }
        return;
    }

    const __nv_bfloat16* Ab = A + (long long)bz * sA + (long long)m0 * Kp;
    const __nv_bfloat16* Bb = B + (long long)bz * sB;

    const uint32_t sbase = s2u(smem);
    const int nk = Kp >> 6;

    // PV: iterate 3 segments x lim tiles; others: nk linear tiles
    int lim, niter;
    if (EPI == EP_PV) {
        lim = m0 / 64 + 2; if (lim > 16) lim = 16;
        niter = 3 * lim;
    } else {
        lim = nk; niter = nk;
    }
    // k-tile index for logical iter j
    #define KOFF(j) ((EPI == EP_PV) ? (((j) / lim) * 16 + ((j) % lim)) : (j))

    // copy coords: 1024 16B-chunks per tile (128 rows x 8 chunks), 4 per thread
    int cr[4], cc[4];
    #pragma unroll
    for (int i = 0; i < 4; i++) { int e = tid + i * 256; cr[i] = e >> 3; cc[i] = e & 7; }

    // hoisted lane-swizzled ldmatrix base offsets (loop-invariant):
    // matrix order per x4: [0]=(r,k) [1]=(r+8,k) [2]=(r,k+8) [3]=(r+8,k+8)
    const int mat = lane >> 3, rr = lane & 7;
    const uint32_t lsw  = (uint32_t)(((mat & 1) * 8 + rr) * SROW + (mat >> 1) * 16);
    const uint32_t aoff = (uint32_t)(wm * 64 * SROW) + lsw;              // A tile
    const uint32_t boff = (uint32_t)(TILE_BYT + wn * 32 * SROW) + lsw;   // B tile

    // ---- prologue: stages 0..NSTG-2 ----
    #pragma unroll
    for (int s = 0; s < NSTG - 1; s++) {
        if (s < niter) {
            const int kk = KOFF(s);
            uint32_t da = sbase + s * STAGE_BYT;
            uint32_t db = da + TILE_BYT;
            #pragma unroll
            for (int i = 0; i < 4; i++) {
                const char* srcA = (const char*)(Ab + (long long)cr[i] * Kp + kk * BKc) + cc[i] * 16;
                cp16(da + cr[i] * SROW + cc[i] * 16, srcA, true);
                bool v = (n0 + cr[i]) < N;
                int rB = v ? (n0 + cr[i]) : 0;
                const char* srcB = (const char*)(Bb + (long long)rB * Kp + kk * BKc) + cc[i] * 16;
                cp16(db + cr[i] * SROW + cc[i] * 16, srcB, v);
            }
        }
        cp_commit();
    }

    float acc[4][4][4] = {};

    for (int j = 0; j < niter; j++) {
        cp_wait1();        // stage j complete (one newer group may stay pending)
        __syncthreads();   // all warps done reading buf[(j-1)%NSTG]

        const int nxt = j + NSTG - 1;
        if (nxt < niter) {
            const int kk = KOFF(nxt);
            uint32_t da = sbase + (nxt % NSTG) * STAGE_BYT;
            uint32_t db = da + TILE_BYT;
            #pragma unroll
            for (int i = 0; i < 4; i++) {
                const char* srcA = (const char*)(Ab + (long long)cr[i] * Kp + kk * BKc) + cc[i] * 16;
                cp16(da + cr[i] * SROW + cc[i] * 16, srcA, true);
                bool v = (n0 + cr[i]) < N;
                int rB = v ? (n0 + cr[i]) : 0;
                const char* srcB = (const char*)(Bb + (long long)rB * Kp + kk * BKc) + cc[i] * 16;
                cp16(db + cr[i] * SROW + cc[i] * 16, srcB, v);
            }
        }
        cp_commit();       // empty-group commits keep wait_group accounting uniform

        const uint32_t bufb = sbase + (uint32_t)((j % NSTG) * STAGE_BYT);
        const uint32_t au   = bufb + aoff;
        const uint32_t bu   = bufb + boff;

        #pragma unroll
        for (int ks = 0; ks < 4; ks++) {
            // A: 4 ldmatrix.x4, addresses = au + immediate
            uint32_t af[4][4];
            #pragma unroll
            for (int fm = 0; fm < 4; fm++)
                ldsm4(af[fm], au + (uint32_t)(fm * 16 * SROW + ks * 32));
            // B: 2 ldmatrix.x4; regs [0]=(n,k) [1]=(n+8,k) [2]=(n,k+8) [3]=(n+8,k+8)
            uint32_t bq[2][4];
            #pragma unroll
            for (int fn = 0; fn < 2; fn++)
                ldsm4(bq[fn], bu + (uint32_t)(fn * 16 * SROW + ks * 32));
            #pragma unroll
            for (int fm = 0; fm < 4; fm++)
                #pragma unroll
                for (int fn = 0; fn < 2; fn++)
                    #pragma unroll
                    for (int sub = 0; sub < 2; sub++)
                        mma16816(acc[fm][fn * 2 + sub], af[fm],
                                 bq[fn][sub], bq[fn][sub + 2]);
        }
    }
    #undef KOFF

    // ---------------- epilogue ----------------
    #pragma unroll
    for (int fm = 0; fm < 4; fm++) {
        const int gmr = m0 + wm * 64 + fm * 16 + (lane >> 2);
        #pragma unroll
        for (int ng = 0; ng < 4; ng++) {
            const int gn = n0 + wn * 32 + ng * 8 + (lane & 3) * 2;
            #pragma unroll
            for (int hh = 0; hh < 2; hh++) {
                const int gm = gmr + hh * 8;
                float v0 = acc[fm][ng][2 * hh];
                float v1 = acc[fm][ng][2 * hh + 1];

                if (EPI == EP_SCORES) {
                    const int   hd    = bz & (Hc - 1);
                    const float slope = exp2f(-0.5f * (float)(hd + 1));
                    float s0 = v0 * 0.125f - slope * fabsf((float)(gm - gn));
                    float s1 = v1 * 0.125f - slope * fabsf((float)(gm - gn - 1));
                    if (gm < gn)     s0 = -10000.0f;
                    if (gm < gn + 1) s1 = -10000.0f;
                    float q0 = rsig(s0); q0 *= q0; s0 = q0 * q0;
                    float q1 = rsig(s1); q1 *= q1; s1 = q1 * q1;
                    __nv_bfloat16 h0, l0, h1, l1;
                    split2(s0, h0, l0); split2(s1, h1, l1);
                    // s3 is an A operand: [hi | lo | hi]
                    __nv_bfloat16* rowp = g_s3 + ((size_t)bz * Tc + gm) * KP_D;
                    uint32_t hp = pack_bf2(__bfloat162float(h0), __bfloat162float(h1));
                    uint32_t lp = pack_bf2(__bfloat162float(l0), __bfloat162float(l1));
                    *(uint32_t*)(rowp + gn)        = hp;
                    *(uint32_t*)(rowp + 1024 + gn) = lp;
                    *(uint32_t*)(rowp + 2048 + gn) = hp;
                } else if (EPI == EP_PV) {
                    if (gn >= N) continue;
                    const float inv = 1.0f / (rdiv[(size_t)bz * Tc + gm] + EPSf);
                    const int b = bz >> 4, hd = bz & 15;
                    float o0 = v0 * inv, o1 = v1 * inv;
                    __nv_bfloat16 h0, l0, h1, l1;
                    split2(o0, h0, l0); split2(o1, h1, l1);
                    // a3 is an A operand: [hi | lo | hi]
                    __nv_bfloat16* rowp = g_a3 + ((size_t)(b * Tc + gm)) * KP_D;
                    const int col = hd * DHc + gn;
                    uint32_t hp = pack_bf2(__bfloat162float(h0), __bfloat162float(h1));
                    uint32_t lp = pack_bf2(__bfloat162float(l0), __bfloat162float(l1));
                    *(uint32_t*)(rowp + col)        = hp;
                    *(uint32_t*)(rowp + 1024 + col) = lp;
                    *(uint32_t*)(rowp + 2048 + col) = hp;
                } else {
                    if (gn >= N) continue;
                    float* cp = C + (size_t)gm * N + gn;
                    if (EPI == EP_ADD) { cp[0] += v0; cp[1] += v1; }
                    else {
                        float2 t; t.x = v0; t.y = v1;
                        *(float2*)cp = t;
                    }
                }
            }
        }
    }
}

// ---------------- elementwise / reduction kernels ----------------

__global__ void embed_kernel(const int* __restrict__ ids, const float* __restrict__ emb)
{
    long long idx = (long long)blockIdx.x * blockDim.x + threadIdx.x;
    if (idx >= (long long)NTc * Dc) return;
    int tok = (int)(idx / Dc);
    int d   = (int)(idx % Dc);
    g_x[idx] = emb[(long long)ids[tok] * Dc + d];
}

// mean-error norm -> A-form split row [hi | lo | hi] at given stride
__global__ void __launch_bounds__(256)
norm_split_kernel(const float* __restrict__ x, const float* __restrict__ w, int stride)
{
    int row = blockIdx.x;
    const float* xr = x + (long long)row * Dc;
    float s = 0.0f;
    for (int d = threadIdx.x; d < Dc; d += 256) s += fabsf(xr[d]);
    #pragma unroll
    for (int off = 16; off > 0; off >>= 1) s += __shfl_xor_sync(0xffffffffu, s, off);
    __shared__ float red[8];
    int wid = threadIdx.x >> 5, lid = threadIdx.x & 31;
    if (lid == 0) red[wid] = s;
    __syncthreads();
    __shared__ float s_inv;
    if (threadIdx.x == 0) {
        float t = 0.0f;
        #pragma unroll
        for (int i = 0; i < 8; i++) t += red[i];
        s_inv = 1.0f / (t * (1.0f / Dc) + EPSf);
    }
    __syncthreads();
    float inv = s_inv;
    __nv_bfloat16* orow = g_a3 + (size_t)row * stride;
    for (int d = threadIdx.x; d < Dc; d += 256) {
        float v = xr[d] * inv * w[d];
        __nv_bfloat16 hi, lo; split2(v, hi, lo);
        orow[d] = hi; orow[1024 + d] = lo; orow[2048 + d] = hi;
    }
}

// weight fp32 [N,K] -> B-form bf16 split [N,Kp]: [hi K | hi K | lo K | zeros]
__global__ void wcvt_kernel(const float* __restrict__ src, __nv_bfloat16* __restrict__ dst,
                            int N, int K, int Kp)
{
    long long idx = (long long)blockIdx.x * blockDim.x + threadIdx.x;
    if (idx >= (long long)N * Kp) return;
    int n = (int)(idx / Kp);
    int c = (int)(idx % Kp);
    __nv_bfloat16 o;
    if (c < 3 * K) {
        int cc = (c < K) ? c : ((c < 2 * K) ? c - K : c - 2 * K);
        float v = src[(long long)n * K + cc];
        __nv_bfloat16 hi, lo; split2(v, hi, lo);
        o = (c >= 2 * K) ? lo : hi;      // B form: segments [hi | hi | lo]
    } else {
        o = __float2bfloat16(0.0f);
    }
    dst[idx] = o;
}

// split qkv fp32 [tok][3072]:
//   q3 (A operand) -> [hi | lo | hi]
//   k3 (B operand) -> [hi | hi | lo]
//   v3 (B operand, transposed) -> [hi | hi | lo]
__global__ void split_qkv_kernel()
{
    long long idx = (long long)blockIdx.x * blockDim.x + threadIdx.x;
    if (idx >= (long long)NTc * 3 * Dc) return;
    int tok = (int)(idx / (3 * Dc));
    int r   = (int)(idx % (3 * Dc));
    int c   = r / Dc;
    int hd  = r % Dc;
    int h   = hd / DHc;
    int d   = hd % DHc;
    int b   = tok / Tc;
    int t   = tok % Tc;
    float v = g_qkv[idx];
    __nv_bfloat16 hi, lo; split2(v, hi, lo);
    size_t bz = (size_t)(b * Hc + h);
    if (c == 0) {
        __nv_bfloat16* rp = g_q3 + (bz * Tc + t) * KP_ATT;
        rp[d] = hi; rp[64 + d] = lo; rp[128 + d] = hi;       // A form
    } else if (c == 1) {
        __nv_bfloat16* rp = g_k3 + (bz * Tc + t) * KP_ATT;
        rp[d] = hi; rp[64 + d] = hi; rp[128 + d] = lo;       // B form
    } else {
        __nv_bfloat16* rp = g_v3 + (bz * DHc + d) * KP_D;
        rp[t] = hi; rp[1024 + t] = hi; rp[2048 + t] = lo;    // B form
    }
}

// rowsum of s4 from A-form split (hi at +0, lo at +1024)
__global__ void __launch_bounds__(256)
rowsum_kernel()
{
    int row = blockIdx.x;                   // 0 .. B*H*T-1
    const __nv_bfloat16* sr = g_s3 + (size_t)row * KP_D;
    float s = 0.0f;
    for (int j = threadIdx.x; j < Tc; j += 256)
        s += __bfloat162float(sr[j]) + __bfloat162float(sr[1024 + j]);
    #pragma unroll
    for (int off = 16; off > 0; off >>= 1) s += __shfl_xor_sync(0xffffffffu, s, off);
    __shared__ float red[8];
    int wid = threadIdx.x >> 5, lid = threadIdx.x & 31;
    if (lid == 0) red[wid] = s;
    __syncthreads();
    if (threadIdx.x == 0) {
        float t = 0.0f;
        #pragma unroll
        for (int i = 0; i < 8; i++) t += red[i];
        g_rs[row] = t;
    }
}

// swiglu: reads g_tmp [tok][5460], writes A-form split rows into g_a3 at stride 8192
__global__ void swiglu_kernel()
{
    long long idx = (long long)blockIdx.x * blockDim.x + threadIdx.x;
    if (idx >= (long long)NTc * DFFc) return;
    int tok = (int)(idx / DFFc);
    int j   = (int)(idx % DFFc);
    float g = g_tmp[(long long)tok * (2 * DFFc) + j];
    float v = g_tmp[(long long)tok * (2 * DFFc) + DFFc + j];
    float o = g * rsig(g) * v;
    __nv_bfloat16 hi, lo; split2(o, hi, lo);
    __nv_bfloat16* rp = g_a3 + (size_t)tok * KP_FF;
    rp[j] = hi; rp[DFFc + j] = lo; rp[2 * DFFc + j] = hi;
    if (j < 2) rp[3 * DFFc + j] = __float2bfloat16(0.0f);   // pad cols 8190/8191
}

// ---------------- host ----------------

template<int EPI>
static void launch_gemm(const __nv_bfloat16* A, const __nv_bfloat16* B, float* C,
                        int M, int N, int Kp, long long sA, long long sB,
                        int batch, const float* rdiv)
{
    cudaFuncSetAttribute(gemm_mma<EPI>, cudaFuncAttributeMaxDynamicSharedMemorySize, SMEM_TOT);
    dim3 grid(M / 128, (N + 127) / 128, batch);
    gemm_mma<EPI><<<grid, 256, SMEM_TOT>>>(A, B, C, M, N, Kp, sA, sB, rdiv);
}

extern "C" void kernel_launch(void* const* d_in, const int* in_sizes, int n_in,
                              void* d_out, int out_size)
{
    const int*   ids   = (const int*)  d_in[0];
    const float* emb   = (const float*)d_in[1];
    const float* qkv_w = (const float*)d_in[2];
    const float* out_w = (const float*)d_in[3];
    const float* n1_w  = (const float*)d_in[4];
    const float* n2_w  = (const float*)d_in[5];
    const float* wm_w  = (const float*)d_in[6];
    const float* w3_w  = (const float*)d_in[7];
    const float* fn_w  = (const float*)d_in[8];
    float* logits = (float*)d_out;

    float *px, *pqkv, *ptmp, *prs;
    __nv_bfloat16 *pa3, *pwb, *pq3, *pk3, *pv3, *ps3;
    cudaGetSymbolAddress((void**)&px,   g_x);
    cudaGetSymbolAddress((void**)&pqkv, g_qkv);
    cudaGetSymbolAddress((void**)&ptmp, g_tmp);
    cudaGetSymbolAddress((void**)&prs,  g_rs);
    cudaGetSymbolAddress((void**)&pa3,  g_a3);
    cudaGetSymbolAddress((void**)&pwb,  g_wb);
    cudaGetSymbolAddress((void**)&pq3,  g_q3);
    cudaGetSymbolAddress((void**)&pk3,  g_k3);
    cudaGetSymbolAddress((void**)&pv3,  g_v3);
    cudaGetSymbolAddress((void**)&ps3,  g_s3);

    const long long nXD = (long long)NTc * Dc;

    embed_kernel<<<(unsigned)((nXD + 255) / 256), 256>>>(ids, emb);

    for (int l = 0; l < Lc; l++) {
        // ---- attention ----
        norm_split_kernel<<<NTc, 256>>>(px, n1_w + (long long)l * Dc, KP_D);

        wcvt_kernel<<<(unsigned)(((long long)3 * Dc * KP_D + 255) / 256), 256>>>(
            qkv_w + (long long)l * 3 * Dc * Dc, pwb, 3 * Dc, Dc, KP_D);
        launch_gemm<EP_NONE>(pa3, pwb, pqkv, NTc, 3 * Dc, KP_D, 0, 0, 1, nullptr);

        split_qkv_kernel<<<(unsigned)(((long long)NTc * 3 * Dc + 255) / 256), 256>>>();

        // scores + alibi + causal + sigmoid^4 -> split bf16
        launch_gemm<EP_SCORES>(pq3, pk3, nullptr, Tc, Tc, KP_ATT,
                               (long long)Tc * KP_ATT, (long long)Tc * KP_ATT,
                               Bc * Hc, nullptr);

        rowsum_kernel<<<Bc * Hc * Tc, 256>>>();

        // (s4 @ V) / rowsum -> merged-head split directly into a3
        launch_gemm<EP_PV>(ps3, pv3, nullptr, Tc, DHc, KP_D,
                           (long long)Tc * KP_D, (long long)DHc * KP_D,
                           Bc * Hc, prs);

        wcvt_kernel<<<(unsigned)(((long long)Dc * KP_D + 255) / 256), 256>>>(
            out_w + (long long)l * Dc * Dc, pwb, Dc, Dc, KP_D);
        launch_gemm<EP_ADD>(pa3, pwb, px, NTc, Dc, KP_D, 0, 0, 1, nullptr);

        // ---- swiglu ffn ----
        norm_split_kernel<<<NTc, 256>>>(px, n2_w + (long long)l * Dc, KP_D);

        wcvt_kernel<<<(unsigned)(((long long)2 * DFFc * KP_D + 255) / 256), 256>>>(
            wm_w + (long long)l * 2 * DFFc * Dc, pwb, 2 * DFFc, Dc, KP_D);
        launch_gemm<EP_NONE>(pa3, pwb, ptmp, NTc, 2 * DFFc, KP_D, 0, 0, 1, nullptr);

        swiglu_kernel<<<(unsigned)(((long long)NTc * DFFc + 255) / 256), 256>>>();

        wcvt_kernel<<<(unsigned)(((long long)Dc * KP_FF + 255) / 256), 256>>>(
            w3_w + (long long)l * Dc * DFFc, pwb, Dc, DFFc, KP_FF);
        launch_gemm<EP_ADD>(pa3, pwb, px, NTc, Dc, KP_FF, 0, 0, 1, nullptr);
    }

    // ---- final norm + logits ----
    norm_split_kernel<<<NTc, 256>>>(px, fn_w, KP_D);

    wcvt_kernel<<<(unsigned)(((long long)Vc * KP_D + 255) / 256), 256>>>(
        emb, pwb, Vc, Dc, KP_D);
    launch_gemm<EP_NONE>(pa3, pwb, logits, NTc, Vc, KP_D, 0, 0, 1, nullptr);
}

// round 17
// speedup vs baseline: 1.6918x; 1.1460x over previous
#include <cuda_runtime.h>
#include <cuda_bf16.h>
#include <math.h>
#include <stdint.h>

// ---------------- problem constants ----------------
#define Bc   2
#define Tc   1024
#define Vc   32000
#define Dc   1024
#define Hc   16
#define Lc   4
#define DHc  64
#define DFFc 2730
#define NTc  (Bc*Tc)
#define EPSf 1e-6f

#define KP_D   3072      // 3*1024
#define KP_FF  8192      // pad(3*2730=8190 -> 8192)
#define KP_ATT 192       // 3*64

// ---------------- scratch (static device globals; no allocs) ----------------
__device__ float g_x  [NTc*Dc];
__device__ float g_tmp[(size_t)NTc*2*DFFc];
__device__ float g_rs [Bc*Hc*Tc];
__device__ __nv_bfloat16 g_a3[(size_t)NTc*KP_FF];          // activation split (A form: hi|lo|hi)
__device__ __nv_bfloat16 g_wb[(size_t)Vc*KP_D];            // weight split (B form: hi|hi|lo)
__device__ __nv_bfloat16 g_q3[(size_t)Bc*Hc*Tc*KP_ATT];    // A form
__device__ __nv_bfloat16 g_k3[(size_t)Bc*Hc*Tc*KP_ATT];    // B form
__device__ __nv_bfloat16 g_v3[(size_t)Bc*Hc*DHc*KP_D];     // B form, V^T [bz][d][3072]
__device__ __nv_bfloat16 g_s3[(size_t)Bc*Hc*Tc*KP_D];      // A form, s4 [bz][t][3072]

__device__ __forceinline__ float rsig(float x) {
    return 0.5f * (x / (fabsf(x) + 1.0f) + 1.0f);
}
__device__ __forceinline__ void split2(float v, __nv_bfloat16& hi, __nv_bfloat16& lo) {
    hi = __float2bfloat16(v);
    lo = __float2bfloat16(v - __bfloat162float(hi));
}
__device__ __forceinline__ uint32_t pack_bf2(float a, float b) {
    __nv_bfloat162 t = __floats2bfloat162_rn(a, b);
    return *reinterpret_cast<uint32_t*>(&t);
}

// ---------------- PTX helpers (sm_80+ baseline) ----------------
__device__ __forceinline__ uint32_t s2u(const void* p) {
    uint32_t a;
    asm("{ .reg .u64 t; cvta.to.shared.u64 t, %1; cvt.u32.u64 %0, t; }" : "=r"(a) : "l"(p));
    return a;
}
__device__ __forceinline__ void cp16(uint32_t dst, const void* src, bool pred) {
    int sz = pred ? 16 : 0;
    asm volatile("cp.async.cg.shared.global [%0], [%1], 16, %2;"
                 :: "r"(dst), "l"(src), "r"(sz) : "memory");
}
__device__ __forceinline__ void cp_commit() {
    asm volatile("cp.async.commit_group;" ::: "memory");
}
__device__ __forceinline__ void cp_wait1() {
    asm volatile("cp.async.wait_group 1;" ::: "memory");
}
__device__ __forceinline__ void mma16816(float* c, const uint32_t* a, uint32_t b0, uint32_t b1) {
    asm volatile("mma.sync.aligned.m16n8k16.row.col.f32.bf16.bf16.f32 "
                 "{%0,%1,%2,%3}, {%4,%5,%6,%7}, {%8,%9}, {%0,%1,%2,%3};"
                 : "+f"(c[0]), "+f"(c[1]), "+f"(c[2]), "+f"(c[3])
                 : "r"(a[0]), "r"(a[1]), "r"(a[2]), "r"(a[3]), "r"(b0), "r"(b1));
}

// ---------------- HMMA GEMM: C[M,N] = A'[M,Kp] @ B'[N,Kp]^T ----------------
// BM=128 BN=128 BK=64. 3-stage cp.async pipeline, one __syncthreads per
// k-iter, 8 warps (2m x 4n), warp tile 64x32, padded smem rows (144B),
// direct u32 fragment loads (measured best: R13/R14; both ldmatrix variants
// regressed). EP_SCORES: fully-masked causal tiles exit with NO writes (the
// masked region is never read: PV truncates k, rowsum is causally bounded).
// EP_PV: k-range truncated per block to keys <= m0+127 within each segment.
// EP_QKV: epilogue writes q3/k3/v3 split forms directly (split_qkv fused).
enum { EP_NONE = 0, EP_ADD = 1, EP_SCORES = 2, EP_PV = 3, EP_QKV = 4 };

#define BKc       64
#define SROW      144                 // 128B data + 16B pad
#define TILE_BYT  (128 * SROW)        // 18432 per operand tile
#define STAGE_BYT (2 * TILE_BYT)      // A + B per stage
#define NSTG      3
#define SMEM_TOT  (NSTG * STAGE_BYT)  // 110592

template<int EPI>
__global__ void __launch_bounds__(256, 2)
gemm_mma(const __nv_bfloat16* __restrict__ A, const __nv_bfloat16* __restrict__ B,
         float* __restrict__ C, int M, int N, int Kp,
         long long sA, long long sB, const float* __restrict__ rdiv)
{
    extern __shared__ __align__(16) char smem[];

    const int tid  = threadIdx.x;
    const int lane = tid & 31, wid = tid >> 5;
    const int wm   = wid >> 2, wn = wid & 3;
    const int bz   = blockIdx.z;
    const int m0   = blockIdx.x * 128;
    const int n0   = blockIdx.y * 128;

    // fully-masked causal tile: nothing downstream ever reads it -> no work
    if (EPI == EP_SCORES && m0 + 127 < n0) return;

    const __nv_bfloat16* Ab = A + (long long)bz * sA + (long long)m0 * Kp;
    const __nv_bfloat16* Bb = B + (long long)bz * sB;

    const uint32_t sbase = s2u(smem);
    const int nk = Kp >> 6;

    // PV: iterate 3 segments x lim tiles; others: nk linear tiles
    int lim, niter;
    if (EPI == EP_PV) {
        lim = m0 / 64 + 2; if (lim > 16) lim = 16;
        niter = 3 * lim;
    } else {
        lim = nk; niter = nk;
    }
    #define KOFF(j) ((EPI == EP_PV) ? (((j) / lim) * 16 + ((j) % lim)) : (j))

    // copy coords: 1024 16B-chunks per tile (128 rows x 8 chunks), 4 per thread
    int cr[4], cc[4];
    #pragma unroll
    for (int i = 0; i < 4; i++) { int e = tid + i * 256; cr[i] = e >> 3; cc[i] = e & 7; }

    // ---- prologue: stages 0..NSTG-2 ----
    #pragma unroll
    for (int s = 0; s < NSTG - 1; s++) {
        if (s < niter) {
            const int kk = KOFF(s);
            uint32_t da = sbase + s * STAGE_BYT;
            uint32_t db = da + TILE_BYT;
            #pragma unroll
            for (int i = 0; i < 4; i++) {
                const char* srcA = (const char*)(Ab + (long long)cr[i] * Kp + kk * BKc) + cc[i] * 16;
                cp16(da + cr[i] * SROW + cc[i] * 16, srcA, true);
                bool v = (n0 + cr[i]) < N;
                int rB = v ? (n0 + cr[i]) : 0;
                const char* srcB = (const char*)(Bb + (long long)rB * Kp + kk * BKc) + cc[i] * 16;
                cp16(db + cr[i] * SROW + cc[i] * 16, srcB, v);
            }
        }
        cp_commit();
    }

    float acc[4][4][4] = {};

    for (int j = 0; j < niter; j++) {
        cp_wait1();        // stage j complete (one newer group may stay pending)
        __syncthreads();   // all warps done reading buf[(j-1)%NSTG]

        const int nxt = j + NSTG - 1;
        if (nxt < niter) {
            const int kk = KOFF(nxt);
            uint32_t da = sbase + (nxt % NSTG) * STAGE_BYT;
            uint32_t db = da + TILE_BYT;
            #pragma unroll
            for (int i = 0; i < 4; i++) {
                const char* srcA = (const char*)(Ab + (long long)cr[i] * Kp + kk * BKc) + cc[i] * 16;
                cp16(da + cr[i] * SROW + cc[i] * 16, srcA, true);
                bool v = (n0 + cr[i]) < N;
                int rB = v ? (n0 + cr[i]) : 0;
                const char* srcB = (const char*)(Bb + (long long)rB * Kp + kk * BKc) + cc[i] * 16;
                cp16(db + cr[i] * SROW + cc[i] * 16, srcB, v);
            }
        }
        cp_commit();       // empty-group commits keep wait_group accounting uniform

        const char* sa = smem + (j % NSTG) * STAGE_BYT;
        const char* sb = sa + TILE_BYT;

        #pragma unroll
        for (int ks = 0; ks < 4; ks++) {
            // A fragments per PTX m16n8k16 A table:
            // reg r: row = base + lane/4 + (r&1)*8 ; k = ks*16 + 2*(lane&3) + (r>>1)*8
            uint32_t af[4][4];
            #pragma unroll
            for (int fm = 0; fm < 4; fm++) {
                const int rbase = wm * 64 + fm * 16 + (lane >> 2);
                const int kb    = ks * 16 + 2 * (lane & 3);
                #pragma unroll
                for (int r = 0; r < 4; r++) {
                    int row = rbase + (r & 1) * 8;
                    int kk  = kb + (r >> 1) * 8;
                    af[fm][r] = *(const uint32_t*)(sa + row * SROW + kk * 2);
                }
            }
            // B fragments: reg r: n = base + lane/4 ; k = ks*16 + 2*(lane&3) + r*8
            uint32_t bf[2][2][2];
            #pragma unroll
            for (int fn = 0; fn < 2; fn++)
                #pragma unroll
                for (int sub = 0; sub < 2; sub++) {
                    const int n = wn * 32 + fn * 16 + sub * 8 + (lane >> 2);
                    const int kb = ks * 16 + 2 * (lane & 3);
                    #pragma unroll
                    for (int r = 0; r < 2; r++)
                        bf[fn][sub][r] = *(const uint32_t*)(sb + n * SROW + (kb + r * 8) * 2);
                }
            #pragma unroll
            for (int fm = 0; fm < 4; fm++)
                #pragma unroll
                for (int fn = 0; fn < 2; fn++)
                    #pragma unroll
                    for (int sub = 0; sub < 2; sub++)
                        mma16816(acc[fm][fn * 2 + sub], af[fm],
                                 bf[fn][sub][0], bf[fn][sub][1]);
        }
    }
    #undef KOFF

    // ---------------- epilogue ----------------
    #pragma unroll
    for (int fm = 0; fm < 4; fm++) {
        const int gmr = m0 + wm * 64 + fm * 16 + (lane >> 2);
        #pragma unroll
        for (int ng = 0; ng < 4; ng++) {
            const int gn = n0 + wn * 32 + ng * 8 + (lane & 3) * 2;
            #pragma unroll
            for (int hh = 0; hh < 2; hh++) {
                const int gm = gmr + hh * 8;
                float v0 = acc[fm][ng][2 * hh];
                float v1 = acc[fm][ng][2 * hh + 1];

                if (EPI == EP_SCORES) {
                    const int   hd    = bz & (Hc - 1);
                    const float slope = exp2f(-0.5f * (float)(hd + 1));
                    float s0 = v0 * 0.125f - slope * fabsf((float)(gm - gn));
                    float s1 = v1 * 0.125f - slope * fabsf((float)(gm - gn - 1));
                    if (gm < gn)     s0 = -10000.0f;
                    if (gm < gn + 1) s1 = -10000.0f;
                    float q0 = rsig(s0); q0 *= q0; s0 = q0 * q0;
                    float q1 = rsig(s1); q1 *= q1; s1 = q1 * q1;
                    __nv_bfloat16 h0, l0, h1, l1;
                    split2(s0, h0, l0); split2(s1, h1, l1);
                    // s3 is an A operand: [hi | lo | hi]
                    __nv_bfloat16* rowp = g_s3 + ((size_t)bz * Tc + gm) * KP_D;
                    uint32_t hp = pack_bf2(__bfloat162float(h0), __bfloat162float(h1));
                    uint32_t lp = pack_bf2(__bfloat162float(l0), __bfloat162float(l1));
                    *(uint32_t*)(rowp + gn)        = hp;
                    *(uint32_t*)(rowp + 1024 + gn) = lp;
                    *(uint32_t*)(rowp + 2048 + gn) = hp;
                } else if (EPI == EP_PV) {
                    if (gn >= N) continue;
                    const float inv = 1.0f / (rdiv[(size_t)bz * Tc + gm] + EPSf);
                    const int b = bz >> 4, hd = bz & 15;
                    float o0 = v0 * inv, o1 = v1 * inv;
                    __nv_bfloat16 h0, l0, h1, l1;
                    split2(o0, h0, l0); split2(o1, h1, l1);
                    // a3 is an A operand: [hi | lo | hi]
                    __nv_bfloat16* rowp = g_a3 + ((size_t)(b * Tc + gm)) * KP_D;
                    const int col = hd * DHc + gn;
                    uint32_t hp = pack_bf2(__bfloat162float(h0), __bfloat162float(h1));
                    uint32_t lp = pack_bf2(__bfloat162float(l0), __bfloat162float(l1));
                    *(uint32_t*)(rowp + col)        = hp;
                    *(uint32_t*)(rowp + 1024 + col) = lp;
                    *(uint32_t*)(rowp + 2048 + col) = hp;
                } else if (EPI == EP_QKV) {
                    // gm = token, gn = column in [0, 3072): 0=q, 1=k, 2=v slab
                    const int c  = gn >> 10;
                    const int hd = gn & 1023;
                    const int h  = hd >> 6, d = hd & 63;   // d even
                    const int b  = gm >> 10, t = gm & 1023;
                    const size_t bzq = (size_t)(b * Hc + h);
                    __nv_bfloat16 h0, l0, h1, l1;
                    split2(v0, h0, l0); split2(v1, h1, l1);
                    if (c == 0) {          // q3: A form [hi | lo | hi]
                        __nv_bfloat16* rp = g_q3 + (bzq * Tc + t) * KP_ATT;
                        uint32_t hp = pack_bf2(__bfloat162float(h0), __bfloat162float(h1));
                        uint32_t lp = pack_bf2(__bfloat162float(l0), __bfloat162float(l1));
                        *(uint32_t*)(rp + d)       = hp;
                        *(uint32_t*)(rp + 64 + d)  = lp;
                        *(uint32_t*)(rp + 128 + d) = hp;
                    } else if (c == 1) {   // k3: B form [hi | hi | lo]
                        __nv_bfloat16* rp = g_k3 + (bzq * Tc + t) * KP_ATT;
                        uint32_t hp = pack_bf2(__bfloat162float(h0), __bfloat162float(h1));
                        uint32_t lp = pack_bf2(__bfloat162float(l0), __bfloat162float(l1));
                        *(uint32_t*)(rp + d)       = hp;
                        *(uint32_t*)(rp + 64 + d)  = hp;
                        *(uint32_t*)(rp + 128 + d) = lp;
                    } else {               // v3: transposed, B form [hi | hi | lo]
                        __nv_bfloat16* rp = g_v3 + (bzq * DHc + d) * KP_D;
                        rp[t] = h0; rp[1024 + t] = h0; rp[2048 + t] = l0;
                        __nv_bfloat16* rp2 = g_v3 + (bzq * DHc + d + 1) * KP_D;
                        rp2[t] = h1; rp2[1024 + t] = h1; rp2[2048 + t] = l1;
                    }
                } else {
                    if (gn >= N) continue;
                    float* cp = C + (size_t)gm * N + gn;
                    if (EPI == EP_ADD) { cp[0] += v0; cp[1] += v1; }
                    else {
                        float2 t; t.x = v0; t.y = v1;
                        *(float2*)cp = t;
                    }
                }
            }
        }
    }
}

// ---------------- elementwise / reduction kernels ----------------

__global__ void embed_kernel(const int* __restrict__ ids, const float* __restrict__ emb)
{
    long long idx = (long long)blockIdx.x * blockDim.x + threadIdx.x;
    if (idx >= (long long)NTc * Dc) return;
    int tok = (int)(idx / Dc);
    int d   = (int)(idx % Dc);
    g_x[idx] = emb[(long long)ids[tok] * Dc + d];
}

// mean-error norm -> A-form split row [hi | lo | hi] at given stride
__global__ void __launch_bounds__(256)
norm_split_kernel(const float* __restrict__ x, const float* __restrict__ w, int stride)
{
    int row = blockIdx.x;
    const float* xr = x + (long long)row * Dc;
    float s = 0.0f;
    for (int d = threadIdx.x; d < Dc; d += 256) s += fabsf(xr[d]);
    #pragma unroll
    for (int off = 16; off > 0; off >>= 1) s += __shfl_xor_sync(0xffffffffu, s, off);
    __shared__ float red[8];
    int wid = threadIdx.x >> 5, lid = threadIdx.x & 31;
    if (lid == 0) red[wid] = s;
    __syncthreads();
    __shared__ float s_inv;
    if (threadIdx.x == 0) {
        float t = 0.0f;
        #pragma unroll
        for (int i = 0; i < 8; i++) t += red[i];
        s_inv = 1.0f / (t * (1.0f / Dc) + EPSf);
    }
    __syncthreads();
    float inv = s_inv;
    __nv_bfloat16* orow = g_a3 + (size_t)row * stride;
    for (int d = threadIdx.x; d < Dc; d += 256) {
        float v = xr[d] * inv * w[d];
        __nv_bfloat16 hi, lo; split2(v, hi, lo);
        orow[d] = hi; orow[1024 + d] = lo; orow[2048 + d] = hi;
    }
}

// weight fp32 [N,K] -> B-form bf16 split [N,Kp]: [hi K | hi K | lo K | zeros]
__global__ void wcvt_kernel(const float* __restrict__ src, __nv_bfloat16* __restrict__ dst,
                            int N, int K, int Kp)
{
    long long idx = (long long)blockIdx.x * blockDim.x + threadIdx.x;
    if (idx >= (long long)N * Kp) return;
    int n = (int)(idx / Kp);
    int c = (int)(idx % Kp);
    __nv_bfloat16 o;
    if (c < 3 * K) {
        int cc = (c < K) ? c : ((c < 2 * K) ? c - K : c - 2 * K);
        float v = src[(long long)n * K + cc];
        __nv_bfloat16 hi, lo; split2(v, hi, lo);
        o = (c >= 2 * K) ? lo : hi;      // B form: segments [hi | hi | lo]
    } else {
        o = __float2bfloat16(0.0f);
    }
    dst[idx] = o;
}

// rowsum of s4 from A-form split (hi at +0, lo at +1024), bounded to the
// causal block end: columns >= (t & ~127) + 128 are never written and are
// mathematically zero (they were exact 0.0 stores before; excluded -> same sum).
__global__ void __launch_bounds__(256)
rowsum_kernel()
{
    int row = blockIdx.x;                   // 0 .. B*H*T-1
    const int t = row & (Tc - 1);
    const int jmax = (t & ~127) + 128;      // <= Tc
    const __nv_bfloat16* sr = g_s3 + (size_t)row * KP_D;
    float s = 0.0f;
    for (int j = threadIdx.x; j < jmax; j += 256)
        s += __bfloat162float(sr[j]) + __bfloat162float(sr[1024 + j]);
    #pragma unroll
    for (int off = 16; off > 0; off >>= 1) s += __shfl_xor_sync(0xffffffffu, s, off);
    __shared__ float red[8];
    int wid = threadIdx.x >> 5, lid = threadIdx.x & 31;
    if (lid == 0) red[wid] = s;
    __syncthreads();
    if (threadIdx.x == 0) {
        float tt = 0.0f;
        #pragma unroll
        for (int i = 0; i < 8; i++) tt += red[i];
        g_rs[row] = tt;
    }
}

// swiglu: reads g_tmp [tok][5460], writes A-form split rows into g_a3 at stride 8192
__global__ void swiglu_kernel()
{
    long long idx = (long long)blockIdx.x * blockDim.x + threadIdx.x;
    if (idx >= (long long)NTc * DFFc) return;
    int tok = (int)(idx / DFFc);
    int j   = (int)(idx % DFFc);
    float g = g_tmp[(long long)tok * (2 * DFFc) + j];
    float v = g_tmp[(long long)tok * (2 * DFFc) + DFFc + j];
    float o = g * rsig(g) * v;
    __nv_bfloat16 hi, lo; split2(o, hi, lo);
    __nv_bfloat16* rp = g_a3 + (size_t)tok * KP_FF;
    rp[j] = hi; rp[DFFc + j] = lo; rp[2 * DFFc + j] = hi;
    if (j < 2) rp[3 * DFFc + j] = __float2bfloat16(0.0f);   // pad cols 8190/8191
}

// ---------------- host ----------------

template<int EPI>
static void launch_gemm(const __nv_bfloat16* A, const __nv_bfloat16* B, float* C,
                        int M, int N, int Kp, long long sA, long long sB,
                        int batch, const float* rdiv)
{
    cudaFuncSetAttribute(gemm_mma<EPI>, cudaFuncAttributeMaxDynamicSharedMemorySize, SMEM_TOT);
    dim3 grid(M / 128, (N + 127) / 128, batch);
    gemm_mma<EPI><<<grid, 256, SMEM_TOT>>>(A, B, C, M, N, Kp, sA, sB, rdiv);
}

extern "C" void kernel_launch(void* const* d_in, const int* in_sizes, int n_in,
                              void* d_out, int out_size)
{
    const int*   ids   = (const int*)  d_in[0];
    const float* emb   = (const float*)d_in[1];
    const float* qkv_w = (const float*)d_in[2];
    const float* out_w = (const float*)d_in[3];
    const float* n1_w  = (const float*)d_in[4];
    const float* n2_w  = (const float*)d_in[5];
    const float* wm_w  = (const float*)d_in[6];
    const float* w3_w  = (const float*)d_in[7];
    const float* fn_w  = (const float*)d_in[8];
    float* logits = (float*)d_out;

    float *px, *ptmp, *prs;
    __nv_bfloat16 *pa3, *pwb, *pq3, *pk3, *pv3, *ps3;
    cudaGetSymbolAddress((void**)&px,   g_x);
    cudaGetSymbolAddress((void**)&ptmp, g_tmp);
    cudaGetSymbolAddress((void**)&prs,  g_rs);
    cudaGetSymbolAddress((void**)&pa3,  g_a3);
    cudaGetSymbolAddress((void**)&pwb,  g_wb);
    cudaGetSymbolAddress((void**)&pq3,  g_q3);
    cudaGetSymbolAddress((void**)&pk3,  g_k3);
    cudaGetSymbolAddress((void**)&pv3,  g_v3);
    cudaGetSymbolAddress((void**)&ps3,  g_s3);

    const long long nXD = (long long)NTc * Dc;

    embed_kernel<<<(unsigned)((nXD + 255) / 256), 256>>>(ids, emb);

    for (int l = 0; l < Lc; l++) {
        // ---- attention ----
        norm_split_kernel<<<NTc, 256>>>(px, n1_w + (long long)l * Dc, KP_D);

        wcvt_kernel<<<(unsigned)(((long long)3 * Dc * KP_D + 255) / 256), 256>>>(
            qkv_w + (long long)l * 3 * Dc * Dc, pwb, 3 * Dc, Dc, KP_D);
        // qkv projection with fused split epilogue -> q3/k3/v3
        launch_gemm<EP_QKV>(pa3, pwb, nullptr, NTc, 3 * Dc, KP_D, 0, 0, 1, nullptr);

        // scores + alibi + causal + sigmoid^4 -> split bf16
        launch_gemm<EP_SCORES>(pq3, pk3, nullptr, Tc, Tc, KP_ATT,
                               (long long)Tc * KP_ATT, (long long)Tc * KP_ATT,
                               Bc * Hc, nullptr);

        rowsum_kernel<<<Bc * Hc * Tc, 256>>>();

        // (s4 @ V) / rowsum -> merged-head split directly into a3
        launch_gemm<EP_PV>(ps3, pv3, nullptr, Tc, DHc, KP_D,
                           (long long)Tc * KP_D, (long long)DHc * KP_D,
                           Bc * Hc, prs);

        wcvt_kernel<<<(unsigned)(((long long)Dc * KP_D + 255) / 256), 256>>>(
            out_w + (long long)l * Dc * Dc, pwb, Dc, Dc, KP_D);
        launch_gemm<EP_ADD>(pa3, pwb, px, NTc, Dc, KP_D, 0, 0, 1, nullptr);

        // ---- swiglu ffn ----
        norm_split_kernel<<<NTc, 256>>>(px, n2_w + (long long)l * Dc, KP_D);

        wcvt_kernel<<<(unsigned)(((long long)2 * DFFc * KP_D + 255) / 256), 256>>>(
            wm_w + (long long)l * 2 * DFFc * Dc, pwb, 2 * DFFc, Dc, KP_D);
        launch_gemm<EP_NONE>(pa3, pwb, ptmp, NTc, 2 * DFFc, KP_D, 0, 0, 1, nullptr);

        swiglu_kernel<<<(unsigned)(((long long)NTc * DFFc + 255) / 256), 256>>>();

        wcvt_kernel<<<(unsigned)(((long long)Dc * KP_FF + 255) / 256), 256>>>(
            w3_w + (long long)l * Dc * DFFc, pwb, Dc, DFFc, KP_FF);
        launch_gemm<EP_ADD>(pa3, pwb, px, NTc, Dc, KP_FF, 0, 0, 1, nullptr);
    }

    // ---- final norm + logits ----
    norm_split_kernel<<<NTc, 256>>>(px, fn_w, KP_D);

    wcvt_kernel<<<(unsigned)(((long long)Vc * KP_D + 255) / 256), 256>>>(
        emb, pwb, Vc, Dc, KP_D);
    launch_gemm<EP_NONE>(pa3, pwb, logits, NTc, Vc, KP_D, 0, 0, 1, nullptr);
}